// round 1
// baseline (speedup 1.0000x reference)
#include <cuda_runtime.h>
#include <math_constants.h>
#include <math.h>

#define Bc 16
#define Tc 1024
#define Sc 2048
#define Cc 256
#define Ec 256
#define NSEL 103     // ceil(2048/20)
#define MS 20
#define STRIDEc 20

// ---------------- scratch (device globals; no allocation allowed) ----------
__device__ float g_h[Bc*Tc*Ec];        // 16 MB; h, then reused as out1
__device__ float g_xmean[Bc*Sc];
__device__ float g_invn[Bc*NSEL];
__device__ float g_aa[Bc*NSEL];
__device__ float g_L[Bc*NSEL*NSEL];
__device__ int   g_mu[Bc*MS];
__device__ float g_kl;

// ---------------- small init / final ---------------------------------------
__global__ void init_k() { g_kl = 0.0f; }
__global__ void final_k(float* klout) { klout[0] = -g_kl; }

// ---------------- GEMM NT with epilogue: out = (A*W^T + bias + add)*scale ---
// A: [M,K] row-major, W: [N,K] row-major. M,N,K multiples of 64/16.
__global__ void gemm_nt_ep(const float* __restrict__ A, const float* __restrict__ W,
                           const float* __restrict__ bias, const float* __restrict__ add,
                           float* __restrict__ out, int M, int N, int K, float scale)
{
    __shared__ float As[16][68];
    __shared__ float Ws[16][68];
    const int m0 = blockIdx.y * 64, n0 = blockIdx.x * 64;
    const int tid = threadIdx.x;
    const int tx = tid & 15, ty = tid >> 4;
    const int lr = tid >> 2;           // 0..63
    const int lc = (tid & 3) << 2;     // 0,4,8,12
    float acc[4][4] = {};

    for (int k0 = 0; k0 < K; k0 += 16) {
        float4 a4 = *(const float4*)(A + (size_t)(m0 + lr) * K + k0 + lc);
        float4 w4 = *(const float4*)(W + (size_t)(n0 + lr) * K + k0 + lc);
        As[lc+0][lr] = a4.x; As[lc+1][lr] = a4.y; As[lc+2][lr] = a4.z; As[lc+3][lr] = a4.w;
        Ws[lc+0][lr] = w4.x; Ws[lc+1][lr] = w4.y; Ws[lc+2][lr] = w4.z; Ws[lc+3][lr] = w4.w;
        __syncthreads();
        #pragma unroll
        for (int kk = 0; kk < 16; kk++) {
            float a[4], w[4];
            #pragma unroll
            for (int i = 0; i < 4; i++) { a[i] = As[kk][ty*4 + i]; w[i] = Ws[kk][tx*4 + i]; }
            #pragma unroll
            for (int i = 0; i < 4; i++)
                #pragma unroll
                for (int j = 0; j < 4; j++)
                    acc[i][j] = fmaf(a[i], w[j], acc[i][j]);
        }
        __syncthreads();
    }
    #pragma unroll
    for (int i = 0; i < 4; i++) {
        int m = m0 + ty*4 + i;
        #pragma unroll
        for (int j = 0; j < 4; j++) {
            int n = n0 + tx*4 + j;
            size_t idx = (size_t)m * N + n;
            out[idx] = (acc[i][j] + bias[n] + add[idx]) * scale;
        }
    }
}

// ---------------- batched GEMM NN: C = alpha * A*B -------------------------
// A: [M,K] row-major, B: [K,N] row-major, per-batch strides.
__global__ void gemm_nn(const float* __restrict__ A, const float* __restrict__ B,
                        float* __restrict__ C, int M, int N, int K,
                        long long sA, long long sB, long long sC, float alpha)
{
    __shared__ float As[16][68];
    __shared__ float Bs[16][68];
    const int b = blockIdx.z;
    A += (size_t)b * sA; B += (size_t)b * sB; C += (size_t)b * sC;
    const int m0 = blockIdx.y * 64, n0 = blockIdx.x * 64;
    const int tid = threadIdx.x;
    const int tx = tid & 15, ty = tid >> 4;
    const int lr = tid >> 2;           // 0..63  (A loader)
    const int lc = (tid & 3) << 2;     // 0..12
    const int kr = tid >> 4;           // 0..15  (B loader)
    const int nc = (tid & 15) << 2;    // 0..60
    float acc[4][4] = {};

    for (int k0 = 0; k0 < K; k0 += 16) {
        float4 a4 = *(const float4*)(A + (size_t)(m0 + lr) * K + k0 + lc);
        As[lc+0][lr] = a4.x; As[lc+1][lr] = a4.y; As[lc+2][lr] = a4.z; As[lc+3][lr] = a4.w;
        float4 b4 = *(const float4*)(B + (size_t)(k0 + kr) * N + n0 + nc);
        *(float4*)&Bs[kr][nc] = b4;
        __syncthreads();
        #pragma unroll
        for (int kk = 0; kk < 16; kk++) {
            float a[4], w[4];
            #pragma unroll
            for (int i = 0; i < 4; i++) { a[i] = As[kk][ty*4 + i]; w[i] = Bs[kk][tx*4 + i]; }
            #pragma unroll
            for (int i = 0; i < 4; i++)
                #pragma unroll
                for (int j = 0; j < 4; j++)
                    acc[i][j] = fmaf(a[i], w[j], acc[i][j]);
        }
        __syncthreads();
    }
    #pragma unroll
    for (int i = 0; i < 4; i++) {
        int m = m0 + ty*4 + i;
        #pragma unroll
        for (int j = 0; j < 4; j++) {
            int n = n0 + tx*4 + j;
            C[(size_t)m * N + n] = alpha * acc[i][j];
        }
    }
}

// ---------------- row softmax (in place), rows of length Sc ----------------
__global__ void softmax_rows(float* __restrict__ attn)
{
    const size_t row = blockIdx.x;
    float* p = attn + row * (size_t)Sc;
    const int tid = threadIdx.x;   // 256 threads, 8 elems each
    __shared__ float red[256];
    float v[8];
    float mx = -CUDART_INF_F;
    #pragma unroll
    for (int i = 0; i < 8; i++) { v[i] = p[tid + i*256]; mx = fmaxf(mx, v[i]); }
    red[tid] = mx; __syncthreads();
    for (int s = 128; s > 0; s >>= 1) { if (tid < s) red[tid] = fmaxf(red[tid], red[tid+s]); __syncthreads(); }
    mx = red[0]; __syncthreads();
    float sum = 0.0f;
    #pragma unroll
    for (int i = 0; i < 8; i++) { v[i] = expf(v[i] - mx); sum += v[i]; }
    red[tid] = sum; __syncthreads();
    for (int s = 128; s > 0; s >>= 1) { if (tid < s) red[tid] += red[tid+s]; __syncthreads(); }
    const float inv = 1.0f / red[0];
    #pragma unroll
    for (int i = 0; i < 8; i++) p[tid + i*256] = v[i] * inv;
}

// ---------------- x_mean[b][s] = mean_t attn[b][t][s] -----------------------
__global__ void xmean_k(const float* __restrict__ attn)
{
    const int b = blockIdx.y;
    const int s = blockIdx.x * 256 + threadIdx.x;
    const float* p = attn + (size_t)b * Tc * Sc + s;
    float sum = 0.0f;
    for (int t = 0; t < Tc; t++) sum += p[(size_t)t * Sc];
    g_xmean[b * Sc + s] = sum * (1.0f / Tc);
}

// ---------------- row inv-norms of strided enc_values + aa -----------------
__global__ void norm_aa_k(const float* __restrict__ V)
{
    const int b = blockIdx.x;
    const int w = threadIdx.x >> 5, lane = threadIdx.x & 31;
    for (int n = w; n < NSEL; n += 8) {
        const float* row = V + ((size_t)b * Sc + (size_t)n * STRIDEc) * Ec;
        float s = 0.0f;
        for (int e = lane; e < Ec; e += 32) { float x = row[e]; s = fmaf(x, x, s); }
        #pragma unroll
        for (int o = 16; o; o >>= 1) s += __shfl_down_sync(0xffffffffu, s, o);
        if (lane == 0) {
            g_invn[b * NSEL + n] = rsqrtf(s);
            g_aa[b * NSEL + n]   = g_xmean[b * Sc + n * STRIDEc];
        }
    }
}

// ---------------- L[b][n][m] = aa_n aa_m * <v_n,v_m>/(|v_n||v_m|) ----------
__global__ void L_k(const float* __restrict__ V)
{
    const int b = blockIdx.x, n = blockIdx.y;
    __shared__ float vn[Ec];
    const float* rn = V + ((size_t)b * Sc + (size_t)n * STRIDEc) * Ec;
    for (int e = threadIdx.x; e < Ec; e += 128) vn[e] = rn[e];
    __syncthreads();
    const int m = threadIdx.x;
    if (m < NSEL) {
        const float* rm = V + ((size_t)b * Sc + (size_t)m * STRIDEc) * Ec;
        float d = 0.0f;
        for (int e = 0; e < Ec; e++) d = fmaf(vn[e], rm[e], d);
        float val = d * g_invn[b*NSEL + n] * g_invn[b*NSEL + m]
                      * g_aa[b*NSEL + n]   * g_aa[b*NSEL + m];
        g_L[((size_t)b * NSEL + n) * NSEL + m] = val;
    }
}

// numpy-style argmax of logf(D[n]*mask[n]): first NaN wins; strict > keeps first max
__device__ __forceinline__ int argmax_logDm(const float* D, const float* msk)
{
    int J = 0; float best = -CUDART_INF_F; bool done = false;
    for (int n = 0; n < NSEL && !done; n++) {
        float v = logf(D[n] * msk[n]);
        if (isnan(v)) { J = n; done = true; }
        else if (v > best) { best = v; J = n; }
    }
    return J;
}

// ---------------- greedy bfgm selection (sequential, tiny) -----------------
__global__ void bfgm_k()
{
    const int b = blockIdx.x, tid = threadIdx.x;  // 128 threads
    __shared__ float Cm[NSEL][MS];
    __shared__ float D[NSEL], msk[NSEL], cjs[MS];
    __shared__ float djs;
    __shared__ int Jsh, sel[MS];
    const float* L = g_L + (size_t)b * NSEL * NSEL;

    if (tid < NSEL) {
        D[tid] = L[(size_t)tid * NSEL + tid];
        msk[tid] = 1.0f;
        #pragma unroll
        for (int k = 0; k < MS; k++) Cm[tid][k] = 0.0f;
    }
    __syncthreads();
    if (tid == 0) {
        int J = argmax_logDm(D, msk);
        Jsh = J; msk[J] = 0.0f; sel[0] = J;
    }
    __syncthreads();

    for (int t = 1; t < MS; t++) {
        const int J = Jsh;
        if (tid < MS) cjs[tid] = Cm[J][tid];
        if (tid == 0) djs = D[J];
        __syncthreads();
        if (tid < NSEL) {
            float Lj = L[(size_t)J * NSEL + tid];
            float cd = 0.0f;
            #pragma unroll
            for (int k = 0; k < MS; k++) cd = fmaf(Cm[tid][k], cjs[k], cd);
            float e = (Lj - cd) / djs * msk[tid];
            Cm[tid][t] = e;
            D[tid] -= e * e;
        }
        __syncthreads();
        if (tid == 0) {
            int Jn = argmax_logDm(D, msk);
            Jsh = Jn; msk[Jn] = 0.0f; sel[t] = Jn;
        }
        __syncthreads();
    }
    if (tid == 0) {
        for (int i = 1; i < MS; i++) {          // insertion sort ascending
            int key = sel[i], j = i - 1;
            while (j >= 0 && sel[j] > key) { sel[j+1] = sel[j]; j--; }
            sel[j+1] = key;
        }
        for (int k = 0; k < MS; k++) g_mu[b*MS + k] = sel[k];
    }
}

// ---------------- gaussian mixture -> softmax(dist) -> KL partial ----------
__global__ void distkl_k()
{
    const int b = blockIdx.x, tid = threadIdx.x;   // 256 threads, 8 s-values each
    __shared__ float red[256];
    int mus[MS];
    #pragma unroll
    for (int k = 0; k < MS; k++) mus[k] = g_mu[b*MS + k];

    float g[8];
    float mx = -CUDART_INF_F;
    #pragma unroll
    for (int i = 0; i < 8; i++) {
        const int s = tid + i*256;
        float acc = 0.0f;
        #pragma unroll
        for (int k = 0; k < MS; k++) {
            float z = (float)s - (float)mus[k];
            acc += expf(-z*z * (1.0f/18.0f));        // 2*sigma^2 = 18
        }
        acc *= 0.13298076013381091f;                 // 1/(sqrt(2pi)*3)
        g[i] = acc; mx = fmaxf(mx, acc);
    }
    red[tid] = mx; __syncthreads();
    for (int s = 128; s > 0; s >>= 1) { if (tid < s) red[tid] = fmaxf(red[tid], red[tid+s]); __syncthreads(); }
    mx = red[0]; __syncthreads();
    float sum = 0.0f;
    #pragma unroll
    for (int i = 0; i < 8; i++) { g[i] = expf(g[i] - mx); sum += g[i]; }
    red[tid] = sum; __syncthreads();
    for (int s = 128; s > 0; s >>= 1) { if (tid < s) red[tid] += red[tid+s]; __syncthreads(); }
    const float inv = 1.0f / red[0];
    __syncthreads();

    float kl = 0.0f;
    #pragma unroll
    for (int i = 0; i < 8; i++) {
        const int s = tid + i*256;
        float xm = g_xmean[b*Sc + s];
        kl += xm * (logf(xm) - g[i] * inv);
    }
    red[tid] = kl; __syncthreads();
    for (int s = 128; s > 0; s >>= 1) { if (tid < s) red[tid] += red[tid+s]; __syncthreads(); }
    if (tid == 0) atomicAdd(&g_kl, red[0]);
}

// ---------------- launch ----------------------------------------------------
extern "C" void kernel_launch(void* const* d_in, const int* in_sizes, int n_in,
                              void* d_out, int out_size)
{
    const float* x  = (const float*)d_in[0];
    const float* te = (const float*)d_in[1];
    const float* ek = (const float*)d_in[2];   // [B,E,S]
    const float* ev = (const float*)d_in[3];   // [B,S,E]
    const float* Wi = (const float*)d_in[4];   // [E,C]
    const float* bi = (const float*)d_in[5];
    const float* Wo = (const float*)d_in[6];   // [C,E]
    const float* bo = (const float*)d_in[7];

    float* out  = (float*)d_out;                              // [B,T,C]
    float* attn = out + (size_t)Bc * Tc * Cc;                 // [B,T,S]
    float* klp  = attn + (size_t)Bc * Tc * Sc;                // scalar

    float* hbuf = nullptr;
    cudaGetSymbolAddress((void**)&hbuf, g_h);

    const float SQ05 = 0.70710678118654752f;
    const float SQS  = 45.25483399593904f;    // s*sqrt(1/s), s=2048

    init_k<<<1, 1>>>();

    // h = (x @ W_in^T + b_in + te) * sqrt(0.5)
    gemm_nt_ep<<<dim3(Ec/64, (Bc*Tc)/64), 256>>>(x, Wi, bi, te, hbuf, Bc*Tc, Ec, Cc, SQ05);

    // scores = h @ enc_keys  (per batch), write into attn region
    gemm_nn<<<dim3(Sc/64, Tc/64, Bc), 256>>>(hbuf, ek, attn, Tc, Sc, Ec,
                                             (long long)Tc*Ec, (long long)Ec*Sc,
                                             (long long)Tc*Sc, 1.0f);

    // attn = softmax(scores) in place
    softmax_rows<<<Bc*Tc, 256>>>(attn);

    // x_mean
    xmean_k<<<dim3(Sc/256, Bc), 256>>>(attn);

    // out1 = attn @ enc_values * sqrt(S)  (reuse hbuf)
    gemm_nn<<<dim3(Ec/64, Tc/64, Bc), 256>>>(attn, ev, hbuf, Tc, Ec, Sc,
                                             (long long)Tc*Sc, (long long)Sc*Ec,
                                             (long long)Tc*Ec, SQS);

    // out = (out1 @ W_out^T + b_out + x) * sqrt(0.5)
    gemm_nt_ep<<<dim3(Cc/64, (Bc*Tc)/64), 256>>>(hbuf, Wo, bo, x, out, Bc*Tc, Cc, Ec, SQ05);

    // DPP side path
    norm_aa_k<<<Bc, 256>>>(ev);
    L_k<<<dim3(Bc, NSEL), 128>>>(ev);
    bfgm_k<<<Bc, 128>>>();
    distkl_k<<<Bc, 256>>>();
    final_k<<<1, 1>>>(klp);
}

// round 2
// speedup vs baseline: 1.2845x; 1.2845x over previous
#include <cuda_runtime.h>
#include <math_constants.h>
#include <math.h>
#include <stdint.h>

#define Bc 16
#define Tc 1024
#define Sc 2048
#define Cc 256
#define Ec 256
#define NSEL 103     // ceil(2048/20)
#define MS 20
#define STRIDEc 20

// ---------------- scratch (device globals; no allocation allowed) ----------
__device__ float g_h[Bc*Tc*Ec];        // 16 MB; h, then reused as out1
__device__ float g_xmean[Bc*Sc];
__device__ float g_invn[Bc*NSEL];
__device__ float g_aa[Bc*NSEL];
__device__ float g_L[Bc*NSEL*NSEL];
__device__ int   g_mu[Bc*MS];
__device__ float g_kl;

// ---------------- small init / final ---------------------------------------
__global__ void init_k() { g_kl = 0.0f; }
__global__ void final_k(float* klout) { klout[0] = -g_kl; }

// ---------------- tf32 split helpers ----------------------------------------
__device__ __forceinline__ void split_tf32(float x, uint32_t& hi, uint32_t& lo)
{
    uint32_t h;
    asm("cvt.rna.tf32.f32 %0, %1;" : "=r"(h) : "f"(x));
    float l = x - __uint_as_float(h);
    uint32_t lb;
    asm("cvt.rna.tf32.f32 %0, %1;" : "=r"(lb) : "f"(l));
    hi = h; lo = lb;
}

#define MMA_TF32(c, a, b) \
    asm volatile("mma.sync.aligned.m16n8k8.row.col.f32.tf32.tf32.f32 " \
        "{%0,%1,%2,%3}, {%4,%5,%6,%7}, {%8,%9}, {%0,%1,%2,%3};" \
        : "+f"((c)[0]), "+f"((c)[1]), "+f"((c)[2]), "+f"((c)[3]) \
        : "r"((a)[0]), "r"((a)[1]), "r"((a)[2]), "r"((a)[3]), \
          "r"((b)[0]), "r"((b)[1]))

__device__ __forceinline__ void cpa16(void* smem_dst, const void* gsrc)
{
    uint32_t d = (uint32_t)__cvta_generic_to_shared(smem_dst);
    asm volatile("cp.async.cg.shared.global [%0], [%1], 16;" :: "r"(d), "l"(gsrc));
}
__device__ __forceinline__ void cpa_commit() { asm volatile("cp.async.commit_group;"); }
__device__ __forceinline__ void cpa_wait0()  { asm volatile("cp.async.wait_group 0;"); }
__device__ __forceinline__ void cpa_wait1()  { asm volatile("cp.async.wait_group 1;"); }

// ============================================================================
// Batched NN GEMM, tensor cores, split-tf32:  C = alpha * A[M,K] @ B[K,N]
// BM=128 BN=64 BK=16, 256 threads (8 warps: 4 in M x 2 in N), warp 32x32
// ============================================================================
__global__ __launch_bounds__(256, 2)
void gemm_nn_tc(const float* __restrict__ A, const float* __restrict__ B,
                float* __restrict__ C, int M, int N, int K,
                long long sA, long long sB, long long sC, float alpha)
{
    const int bz = blockIdx.z;
    A += (size_t)bz * sA; B += (size_t)bz * sB; C += (size_t)bz * sC;
    const int m0 = blockIdx.y * 128, n0 = blockIdx.x * 64;
    const int tid = threadIdx.x, lane = tid & 31, wid = tid >> 5;
    const int wm = (wid & 3) * 32, wn = (wid >> 2) * 32;
    const int g = lane >> 2, t = lane & 3;

    __shared__ float As[2][128][20];
    __shared__ float Bs[2][16][72];

    float c[2][4][4] = {};

    const int S = K / 16;

    // --- stage issue lambda (A: 2 chunks/thread, B: 1 chunk/thread) ---
    auto issue = [&](int s, int buf) {
        const int k0 = s * 16;
        #pragma unroll
        for (int j = 0; j < 2; j++) {
            int ch = tid + j * 256;
            int row = ch >> 2, kc = ch & 3;
            cpa16(&As[buf][row][kc * 4], A + (size_t)(m0 + row) * K + k0 + kc * 4);
        }
        int brow = tid >> 4, bnc = tid & 15;
        cpa16(&Bs[buf][brow][bnc * 4], B + (size_t)(k0 + brow) * N + n0 + bnc * 4);
        cpa_commit();
    };

    issue(0, 0);
    for (int s = 0; s < S; s++) {
        if (s + 1 < S) { issue(s + 1, (s + 1) & 1); cpa_wait1(); }
        else cpa_wait0();
        __syncthreads();
        const int buf = s & 1;
        #pragma unroll
        for (int kf = 0; kf < 2; kf++) {
            uint32_t ah[2][4], al[2][4];
            #pragma unroll
            for (int mt = 0; mt < 2; mt++) {
                int mr = wm + mt * 16 + g;
                float a0 = As[buf][mr    ][kf*8 + t];
                float a1 = As[buf][mr + 8][kf*8 + t];
                float a2 = As[buf][mr    ][kf*8 + t + 4];
                float a3 = As[buf][mr + 8][kf*8 + t + 4];
                split_tf32(a0, ah[mt][0], al[mt][0]);
                split_tf32(a1, ah[mt][1], al[mt][1]);
                split_tf32(a2, ah[mt][2], al[mt][2]);
                split_tf32(a3, ah[mt][3], al[mt][3]);
            }
            uint32_t bh[4][2], bl[4][2];
            #pragma unroll
            for (int nt = 0; nt < 4; nt++) {
                int nc = wn + nt * 8 + g;
                float b0 = Bs[buf][kf*8 + t    ][nc];
                float b1 = Bs[buf][kf*8 + t + 4][nc];
                split_tf32(b0, bh[nt][0], bl[nt][0]);
                split_tf32(b1, bh[nt][1], bl[nt][1]);
            }
            #pragma unroll
            for (int mt = 0; mt < 2; mt++)
                #pragma unroll
                for (int nt = 0; nt < 4; nt++) {
                    MMA_TF32(c[mt][nt], ah[mt], bh[nt]);
                    MMA_TF32(c[mt][nt], ah[mt], bl[nt]);
                    MMA_TF32(c[mt][nt], al[mt], bh[nt]);
                }
        }
        __syncthreads();
    }

    #pragma unroll
    for (int mt = 0; mt < 2; mt++)
        #pragma unroll
        for (int nt = 0; nt < 4; nt++) {
            int row = m0 + wm + mt * 16 + g;
            int col = n0 + wn + nt * 8 + 2 * t;
            float2 v0 = make_float2(alpha * c[mt][nt][0], alpha * c[mt][nt][1]);
            float2 v1 = make_float2(alpha * c[mt][nt][2], alpha * c[mt][nt][3]);
            *(float2*)&C[(size_t)row * N + col]       = v0;
            *(float2*)&C[(size_t)(row + 8) * N + col] = v1;
        }
}

// ============================================================================
// NT GEMM with epilogue: out = (A[M,K] @ W[N,K]^T + bias + add) * scale
// ============================================================================
__global__ __launch_bounds__(256, 2)
void gemm_nt_tc(const float* __restrict__ A, const float* __restrict__ W,
                const float* __restrict__ bias, const float* __restrict__ add,
                float* __restrict__ out, int M, int N, int K, float scale)
{
    const int m0 = blockIdx.y * 128, n0 = blockIdx.x * 64;
    const int tid = threadIdx.x, lane = tid & 31, wid = tid >> 5;
    const int wm = (wid & 3) * 32, wn = (wid >> 2) * 32;
    const int g = lane >> 2, t = lane & 3;

    __shared__ float As[2][128][20];
    __shared__ float Ws[2][64][20];

    float c[2][4][4] = {};
    const int S = K / 16;

    auto issue = [&](int s, int buf) {
        const int k0 = s * 16;
        #pragma unroll
        for (int j = 0; j < 2; j++) {
            int ch = tid + j * 256;
            int row = ch >> 2, kc = ch & 3;
            cpa16(&As[buf][row][kc * 4], A + (size_t)(m0 + row) * K + k0 + kc * 4);
        }
        int wrow = tid >> 2, wkc = tid & 3;
        cpa16(&Ws[buf][wrow][wkc * 4], W + (size_t)(n0 + wrow) * K + k0 + wkc * 4);
        cpa_commit();
    };

    issue(0, 0);
    for (int s = 0; s < S; s++) {
        if (s + 1 < S) { issue(s + 1, (s + 1) & 1); cpa_wait1(); }
        else cpa_wait0();
        __syncthreads();
        const int buf = s & 1;
        #pragma unroll
        for (int kf = 0; kf < 2; kf++) {
            uint32_t ah[2][4], al[2][4];
            #pragma unroll
            for (int mt = 0; mt < 2; mt++) {
                int mr = wm + mt * 16 + g;
                float a0 = As[buf][mr    ][kf*8 + t];
                float a1 = As[buf][mr + 8][kf*8 + t];
                float a2 = As[buf][mr    ][kf*8 + t + 4];
                float a3 = As[buf][mr + 8][kf*8 + t + 4];
                split_tf32(a0, ah[mt][0], al[mt][0]);
                split_tf32(a1, ah[mt][1], al[mt][1]);
                split_tf32(a2, ah[mt][2], al[mt][2]);
                split_tf32(a3, ah[mt][3], al[mt][3]);
            }
            uint32_t bh[4][2], bl[4][2];
            #pragma unroll
            for (int nt = 0; nt < 4; nt++) {
                int nr = wn + nt * 8 + g;
                float b0 = Ws[buf][nr][kf*8 + t];
                float b1 = Ws[buf][nr][kf*8 + t + 4];
                split_tf32(b0, bh[nt][0], bl[nt][0]);
                split_tf32(b1, bh[nt][1], bl[nt][1]);
            }
            #pragma unroll
            for (int mt = 0; mt < 2; mt++)
                #pragma unroll
                for (int nt = 0; nt < 4; nt++) {
                    MMA_TF32(c[mt][nt], ah[mt], bh[nt]);
                    MMA_TF32(c[mt][nt], ah[mt], bl[nt]);
                    MMA_TF32(c[mt][nt], al[mt], bh[nt]);
                }
        }
        __syncthreads();
    }

    #pragma unroll
    for (int mt = 0; mt < 2; mt++)
        #pragma unroll
        for (int nt = 0; nt < 4; nt++) {
            int row = m0 + wm + mt * 16 + g;
            int col = n0 + wn + nt * 8 + 2 * t;
            float2 bv = *(const float2*)&bias[col];
            size_t i0 = (size_t)row * N + col;
            size_t i1 = (size_t)(row + 8) * N + col;
            float2 d0 = *(const float2*)&add[i0];
            float2 d1 = *(const float2*)&add[i1];
            float2 v0 = make_float2((c[mt][nt][0] + bv.x + d0.x) * scale,
                                    (c[mt][nt][1] + bv.y + d0.y) * scale);
            float2 v1 = make_float2((c[mt][nt][2] + bv.x + d1.x) * scale,
                                    (c[mt][nt][3] + bv.y + d1.y) * scale);
            *(float2*)&out[i0] = v0;
            *(float2*)&out[i1] = v1;
        }
}

// ---------------- row softmax (in place), rows of length Sc ----------------
__global__ void softmax_rows(float* __restrict__ attn)
{
    const size_t row = blockIdx.x;
    float* p = attn + row * (size_t)Sc;
    const int tid = threadIdx.x;   // 256 threads, 8 elems each
    __shared__ float red[256];
    float v[8];
    float mx = -CUDART_INF_F;
    #pragma unroll
    for (int i = 0; i < 8; i++) { v[i] = p[tid + i*256]; mx = fmaxf(mx, v[i]); }
    red[tid] = mx; __syncthreads();
    for (int s = 128; s > 0; s >>= 1) { if (tid < s) red[tid] = fmaxf(red[tid], red[tid+s]); __syncthreads(); }
    mx = red[0]; __syncthreads();
    float sum = 0.0f;
    #pragma unroll
    for (int i = 0; i < 8; i++) { v[i] = expf(v[i] - mx); sum += v[i]; }
    red[tid] = sum; __syncthreads();
    for (int s = 128; s > 0; s >>= 1) { if (tid < s) red[tid] += red[tid+s]; __syncthreads(); }
    const float inv = 1.0f / red[0];
    #pragma unroll
    for (int i = 0; i < 8; i++) p[tid + i*256] = v[i] * inv;
}

// ---------------- x_mean[b][s] = mean_t attn[b][t][s] -----------------------
__global__ void xmean_k(const float* __restrict__ attn)
{
    const int b = blockIdx.y;
    const int s = blockIdx.x * 256 + threadIdx.x;
    const float* p = attn + (size_t)b * Tc * Sc + s;
    float sum = 0.0f;
    for (int t = 0; t < Tc; t++) sum += p[(size_t)t * Sc];
    g_xmean[b * Sc + s] = sum * (1.0f / Tc);
}

// ---------------- row inv-norms of strided enc_values + aa -----------------
__global__ void norm_aa_k(const float* __restrict__ V)
{
    const int b = blockIdx.x;
    const int w = threadIdx.x >> 5, lane = threadIdx.x & 31;
    for (int n = w; n < NSEL; n += 8) {
        const float* row = V + ((size_t)b * Sc + (size_t)n * STRIDEc) * Ec;
        float s = 0.0f;
        for (int e = lane; e < Ec; e += 32) { float x = row[e]; s = fmaf(x, x, s); }
        #pragma unroll
        for (int o = 16; o; o >>= 1) s += __shfl_down_sync(0xffffffffu, s, o);
        if (lane == 0) {
            g_invn[b * NSEL + n] = rsqrtf(s);
            g_aa[b * NSEL + n]   = g_xmean[b * Sc + n * STRIDEc];
        }
    }
}

// ---------------- L[b][n][m] = aa_n aa_m * <v_n,v_m>/(|v_n||v_m|) ----------
__global__ void L_k(const float* __restrict__ V)
{
    const int b = blockIdx.x, n = blockIdx.y;
    __shared__ float vn[Ec];
    const float* rn = V + ((size_t)b * Sc + (size_t)n * STRIDEc) * Ec;
    for (int e = threadIdx.x; e < Ec; e += 128) vn[e] = rn[e];
    __syncthreads();
    const int m = threadIdx.x;
    if (m < NSEL) {
        const float* rm = V + ((size_t)b * Sc + (size_t)m * STRIDEc) * Ec;
        float d = 0.0f;
        for (int e = 0; e < Ec; e++) d = fmaf(vn[e], rm[e], d);
        float val = d * g_invn[b*NSEL + n] * g_invn[b*NSEL + m]
                      * g_aa[b*NSEL + n]   * g_aa[b*NSEL + m];
        g_L[((size_t)b * NSEL + n) * NSEL + m] = val;
    }
}

// numpy-style argmax of logf(D[n]*mask[n]): first NaN wins; strict > keeps first max
__device__ __forceinline__ int argmax_logDm(const float* D, const float* msk)
{
    int J = 0; float best = -CUDART_INF_F; bool done = false;
    for (int n = 0; n < NSEL && !done; n++) {
        float v = logf(D[n] * msk[n]);
        if (isnan(v)) { J = n; done = true; }
        else if (v > best) { best = v; J = n; }
    }
    return J;
}

// ---------------- greedy bfgm selection (sequential, tiny) -----------------
__global__ void bfgm_k()
{
    const int b = blockIdx.x, tid = threadIdx.x;  // 128 threads
    __shared__ float Cm[NSEL][MS];
    __shared__ float D[NSEL], msk[NSEL], cjs[MS];
    __shared__ float djs;
    __shared__ int Jsh, sel[MS];
    const float* L = g_L + (size_t)b * NSEL * NSEL;

    if (tid < NSEL) {
        D[tid] = L[(size_t)tid * NSEL + tid];
        msk[tid] = 1.0f;
        #pragma unroll
        for (int k = 0; k < MS; k++) Cm[tid][k] = 0.0f;
    }
    __syncthreads();
    if (tid == 0) {
        int J = argmax_logDm(D, msk);
        Jsh = J; msk[J] = 0.0f; sel[0] = J;
    }
    __syncthreads();

    for (int t = 1; t < MS; t++) {
        const int J = Jsh;
        if (tid < MS) cjs[tid] = Cm[J][tid];
        if (tid == 0) djs = D[J];
        __syncthreads();
        if (tid < NSEL) {
            float Lj = L[(size_t)J * NSEL + tid];
            float cd = 0.0f;
            #pragma unroll
            for (int k = 0; k < MS; k++) cd = fmaf(Cm[tid][k], cjs[k], cd);
            float e = (Lj - cd) / djs * msk[tid];
            Cm[tid][t] = e;
            D[tid] -= e * e;
        }
        __syncthreads();
        if (tid == 0) {
            int Jn = argmax_logDm(D, msk);
            Jsh = Jn; msk[Jn] = 0.0f; sel[t] = Jn;
        }
        __syncthreads();
    }
    if (tid == 0) {
        for (int i = 1; i < MS; i++) {          // insertion sort ascending
            int key = sel[i], j = i - 1;
            while (j >= 0 && sel[j] > key) { sel[j+1] = sel[j]; j--; }
            sel[j+1] = key;
        }
        for (int k = 0; k < MS; k++) g_mu[b*MS + k] = sel[k];
    }
}

// ---------------- gaussian mixture -> softmax(dist) -> KL partial ----------
__global__ void distkl_k()
{
    const int b = blockIdx.x, tid = threadIdx.x;   // 256 threads, 8 s-values each
    __shared__ float red[256];
    int mus[MS];
    #pragma unroll
    for (int k = 0; k < MS; k++) mus[k] = g_mu[b*MS + k];

    float g[8];
    float mx = -CUDART_INF_F;
    #pragma unroll
    for (int i = 0; i < 8; i++) {
        const int s = tid + i*256;
        float acc = 0.0f;
        #pragma unroll
        for (int k = 0; k < MS; k++) {
            float z = (float)s - (float)mus[k];
            acc += expf(-z*z * (1.0f/18.0f));        // 2*sigma^2 = 18
        }
        acc *= 0.13298076013381091f;                 // 1/(sqrt(2pi)*3)
        g[i] = acc; mx = fmaxf(mx, acc);
    }
    red[tid] = mx; __syncthreads();
    for (int s = 128; s > 0; s >>= 1) { if (tid < s) red[tid] = fmaxf(red[tid], red[tid+s]); __syncthreads(); }
    mx = red[0]; __syncthreads();
    float sum = 0.0f;
    #pragma unroll
    for (int i = 0; i < 8; i++) { g[i] = expf(g[i] - mx); sum += g[i]; }
    red[tid] = sum; __syncthreads();
    for (int s = 128; s > 0; s >>= 1) { if (tid < s) red[tid] += red[tid+s]; __syncthreads(); }
    const float inv = 1.0f / red[0];
    __syncthreads();

    float kl = 0.0f;
    #pragma unroll
    for (int i = 0; i < 8; i++) {
        const int s = tid + i*256;
        float xm = g_xmean[b*Sc + s];
        kl += xm * (logf(xm) - g[i] * inv);
    }
    red[tid] = kl; __syncthreads();
    for (int s = 128; s > 0; s >>= 1) { if (tid < s) red[tid] += red[tid+s]; __syncthreads(); }
    if (tid == 0) atomicAdd(&g_kl, red[0]);
}

// ---------------- launch ----------------------------------------------------
extern "C" void kernel_launch(void* const* d_in, const int* in_sizes, int n_in,
                              void* d_out, int out_size)
{
    const float* x  = (const float*)d_in[0];
    const float* te = (const float*)d_in[1];
    const float* ek = (const float*)d_in[2];   // [B,E,S]
    const float* ev = (const float*)d_in[3];   // [B,S,E]
    const float* Wi = (const float*)d_in[4];   // [E,C]
    const float* bi = (const float*)d_in[5];
    const float* Wo = (const float*)d_in[6];   // [C,E]
    const float* bo = (const float*)d_in[7];

    float* out  = (float*)d_out;                              // [B,T,C]
    float* attn = out + (size_t)Bc * Tc * Cc;                 // [B,T,S]
    float* klp  = attn + (size_t)Bc * Tc * Sc;                // scalar

    float* hbuf = nullptr;
    cudaGetSymbolAddress((void**)&hbuf, g_h);

    const float SQ05 = 0.70710678118654752f;
    const float SQS  = 45.25483399593904f;    // s*sqrt(1/s), s=2048

    init_k<<<1, 1>>>();

    // h = (x @ W_in^T + b_in + te) * sqrt(0.5)
    gemm_nt_tc<<<dim3(Ec/64, (Bc*Tc)/128), 256>>>(x, Wi, bi, te, hbuf, Bc*Tc, Ec, Cc, SQ05);

    // scores = h @ enc_keys  (per batch), write into attn region
    gemm_nn_tc<<<dim3(Sc/64, Tc/128, Bc), 256>>>(hbuf, ek, attn, Tc, Sc, Ec,
                                                 (long long)Tc*Ec, (long long)Ec*Sc,
                                                 (long long)Tc*Sc, 1.0f);

    // attn = softmax(scores) in place
    softmax_rows<<<Bc*Tc, 256>>>(attn);

    // x_mean
    xmean_k<<<dim3(Sc/256, Bc), 256>>>(attn);

    // out1 = attn @ enc_values * sqrt(S)  (reuse hbuf)
    gemm_nn_tc<<<dim3(Ec/64, Tc/128, Bc), 256>>>(attn, ev, hbuf, Tc, Ec, Sc,
                                                 (long long)Tc*Sc, (long long)Sc*Ec,
                                                 (long long)Tc*Ec, SQS);

    // out = (out1 @ W_out^T + b_out + x) * sqrt(0.5)
    gemm_nt_tc<<<dim3(Cc/64, (Bc*Tc)/128), 256>>>(hbuf, Wo, bo, x, out, Bc*Tc, Cc, Ec, SQ05);

    // DPP side path
    norm_aa_k<<<Bc, 256>>>(ev);
    L_k<<<dim3(Bc, NSEL), 128>>>(ev);
    bfgm_k<<<Bc, 128>>>();
    distkl_k<<<Bc, 256>>>();
    final_k<<<1, 1>>>(klp);
}